// round 1
// baseline (speedup 1.0000x reference)
#include <cuda_runtime.h>

#define BATCH 65536
#define D 128
#define NBASIS 6
#define OUTW 896          // D*6 + D
#define ROWS 32           // batch rows per block
#define THREADS 256
#define XS_STRIDE 129     // padded row stride for x_s (conflict-free column reads)

__device__ float g_S[D * D];   // sigmoid(W), row-major [i][j]

// ---------------- f32x2 packed-FMA helpers (Blackwell FFMA2) ----------------
__device__ __forceinline__ unsigned long long pack2(float lo, float hi) {
    unsigned long long r;
    asm("mov.b64 %0, {%1, %2};" : "=l"(r) : "f"(lo), "f"(hi));
    return r;
}
__device__ __forceinline__ unsigned long long fma2(unsigned long long a,
                                                   unsigned long long b,
                                                   unsigned long long c) {
    unsigned long long d;
    asm("fma.rn.f32x2 %0, %1, %2, %3;" : "=l"(d) : "l"(a), "l"(b), "l"(c));
    return d;
}
__device__ __forceinline__ void unpack2(unsigned long long v, float& lo, float& hi) {
    asm("mov.b64 {%0, %1}, %2;" : "=f"(lo), "=f"(hi) : "l"(v));
}

// ---------------- kernel 1: S = sigmoid(W) ----------------
__global__ void sigmoid_kernel(const float* __restrict__ W) {
    int idx = blockIdx.x * blockDim.x + threadIdx.x;
    if (idx < D * D) {
        float w = W[idx];
        g_S[idx] = 1.0f / (1.0f + expf(-w));
    }
}

// ---------------- kernel 2: fused basis + interaction ----------------
__global__ __launch_bounds__(THREADS) void kan_kernel(const float* __restrict__ x,
                                                      float* __restrict__ out) {
    __shared__ float x_s[ROWS * XS_STRIDE];   // raw x tile, padded
    __shared__ float x2p_s[D * ROWS];         // x^2, transposed: [i][row]

    const int tid = threadIdx.x;
    const int r0 = blockIdx.x * ROWS;

    // ---- load x tile: 32 rows x 128 f32 = 1024 float4 (coalesced) ----
    const float4* xg = (const float4*)(x + (size_t)r0 * D);
#pragma unroll
    for (int k = 0; k < 4; k++) {
        int q = tid + k * 256;              // 0..1023
        int row = q >> 5;
        int c4 = q & 31;
        float4 v = xg[row * 32 + c4];
        float* dst = &x_s[row * XS_STRIDE + c4 * 4];
        dst[0] = v.x; dst[1] = v.y; dst[2] = v.z; dst[3] = v.w;
    }
    __syncthreads();

    // ---- transpose + square into x2p_s (conflict-free writes) ----
#pragma unroll
    for (int k = 0; k < 16; k++) {
        int idx = tid + k * 256;            // 0..4095
        int row = idx & 31;                 // lanes span rows -> STS conflict-free
        int i = idx >> 5;
        float v = x_s[row * XS_STRIDE + i]; // stride 129 -> LDS conflict-free
        x2p_s[i * ROWS + row] = v * v;
    }
    __syncthreads();

    // ---- phase A: B-spline basis (uniform cubic, closed form) ----
    // out[b, i*6 + k]; 4096 elements / block, lanes over consecutive i.
    const float s6 = 1.0f / 6.0f;
    const float xmax = 1.0f - 1e-6f;
#pragma unroll 4
    for (int k = 0; k < 16; k++) {
        int e = tid + k * 256;
        int row = e >> 7;
        int i = e & 127;
        float xv = x_s[row * XS_STRIDE + i];
        float xc = fminf(fmaxf(xv, -1.0f), xmax);
        float p = (xc + 1.0f) * 4.5f;       // knot spacing h = 2/9
        int j = (int)p;
        j = max(0, min(j, 8));
        float u = p - (float)j;
        float u2 = u * u;
        float u3 = u2 * u;
        float om = 1.0f - u;
        float N0 = om * om * om * s6;                              // k = j-3
        float N1 = (3.0f * u3 - 6.0f * u2 + 4.0f) * s6;            // k = j-2
        float N2 = (-3.0f * u3 + 3.0f * u2 + 3.0f * u + 1.0f) * s6;// k = j-1
        float N3 = u3 * s6;                                        // k = j
        float v[6];
#pragma unroll
        for (int kk = 0; kk < 6; kk++) {
            int r = kk - j + 3;
            float val = 0.0f;
            val = (r == 0) ? N0 : val;
            val = (r == 1) ? N1 : val;
            val = (r == 2) ? N2 : val;
            val = (r == 3) ? N3 : val;
            v[kk] = val;
        }
        float2* op = (float2*)(out + (size_t)(r0 + row) * OUTW + i * 6);
        op[0] = make_float2(v[0], v[1]);
        op[1] = make_float2(v[2], v[3]);
        op[2] = make_float2(v[4], v[5]);
    }

    // ---- phase B: interaction GEMM  out[b, 768+c] = sum_i x2[b,i]*S[i,c] ----
    const int c = tid & 127;       // output column
    const int g = tid >> 7;        // row-half: 0 -> rows 0..15, 1 -> rows 16..31
    const int rbase = g * 16;

    unsigned long long a0 = 0ull, a1 = 0ull, a2 = 0ull, a3 = 0ull,
                       a4 = 0ull, a5 = 0ull, a6 = 0ull, a7 = 0ull;

#pragma unroll 4
    for (int i = 0; i < D; i++) {
        float s = __ldg(&g_S[i * D + c]);   // coalesced, L1-resident
        unsigned long long s2 = pack2(s, s);
        const ulonglong2* xp = (const ulonglong2*)&x2p_s[i * ROWS + rbase];
        ulonglong2 p0 = xp[0];              // rows rbase+0..3  (broadcast LDS.128)
        ulonglong2 p1 = xp[1];              // rows rbase+4..7
        ulonglong2 p2 = xp[2];              // rows rbase+8..11
        ulonglong2 p3 = xp[3];              // rows rbase+12..15
        a0 = fma2(p0.x, s2, a0);
        a1 = fma2(p0.y, s2, a1);
        a2 = fma2(p1.x, s2, a2);
        a3 = fma2(p1.y, s2, a3);
        a4 = fma2(p2.x, s2, a4);
        a5 = fma2(p2.y, s2, a5);
        a6 = fma2(p3.x, s2, a6);
        a7 = fma2(p3.y, s2, a7);
    }

    float lo, hi;
    float* ob = out + 768 + c;
    size_t rs = (size_t)(r0 + rbase) * OUTW;
    unpack2(a0, lo, hi); ob[rs] = lo;            ob[rs + OUTW] = hi;
    unpack2(a1, lo, hi); ob[rs + 2*OUTW] = lo;   ob[rs + 3*OUTW] = hi;
    unpack2(a2, lo, hi); ob[rs + 4*OUTW] = lo;   ob[rs + 5*OUTW] = hi;
    unpack2(a3, lo, hi); ob[rs + 6*OUTW] = lo;   ob[rs + 7*OUTW] = hi;
    unpack2(a4, lo, hi); ob[rs + 8*OUTW] = lo;   ob[rs + 9*OUTW] = hi;
    unpack2(a5, lo, hi); ob[rs + 10*OUTW] = lo;  ob[rs + 11*OUTW] = hi;
    unpack2(a6, lo, hi); ob[rs + 12*OUTW] = lo;  ob[rs + 13*OUTW] = hi;
    unpack2(a7, lo, hi); ob[rs + 14*OUTW] = lo;  ob[rs + 15*OUTW] = hi;
}

extern "C" void kernel_launch(void* const* d_in, const int* in_sizes, int n_in,
                              void* d_out, int out_size) {
    // x is [65536,128] (8388608 elems), W is [128,128] (16384 elems)
    const float* x;
    const float* W;
    if (n_in >= 2 && in_sizes[0] == D * D && in_sizes[1] != D * D) {
        W = (const float*)d_in[0];
        x = (const float*)d_in[1];
    } else {
        x = (const float*)d_in[0];
        W = (const float*)d_in[1];
    }
    float* out = (float*)d_out;

    sigmoid_kernel<<<(D * D + 255) / 256, 256>>>(W);
    kan_kernel<<<BATCH / ROWS, THREADS>>>(x, out);
}

// round 2
// speedup vs baseline: 1.0057x; 1.0057x over previous
#include <cuda_runtime.h>

#define BATCH 65536
#define D 128
#define OUTW 896          // D*6 + D
#define ROWS 32           // batch rows per block
#define THREADS 256
#define XS_STRIDE 129     // padded row stride for x_s (conflict-free column reads)
#define SLOTS_PER_ROW 384 // 768 basis floats per row = 384 float2 slots
#define TOTAL_SLOTS (ROWS * SLOTS_PER_ROW)   // 12288 per block

__device__ float g_S[D * D];   // sigmoid(W), row-major [i][j]

// ---------------- f32x2 packed-FMA helpers (Blackwell FFMA2) ----------------
__device__ __forceinline__ unsigned long long pack2(float lo, float hi) {
    unsigned long long r;
    asm("mov.b64 %0, {%1, %2};" : "=l"(r) : "f"(lo), "f"(hi));
    return r;
}
__device__ __forceinline__ unsigned long long fma2(unsigned long long a,
                                                   unsigned long long b,
                                                   unsigned long long c) {
    unsigned long long d;
    asm("fma.rn.f32x2 %0, %1, %2, %3;" : "=l"(d) : "l"(a), "l"(b), "l"(c));
    return d;
}
__device__ __forceinline__ void unpack2(unsigned long long v, float& lo, float& hi) {
    asm("mov.b64 {%0, %1}, %2;" : "=f"(lo), "=f"(hi) : "l"(v));
}

// ---------------- kernel 1: S = sigmoid(W) ----------------
__global__ void sigmoid_kernel(const float* __restrict__ W) {
    int idx = blockIdx.x * blockDim.x + threadIdx.x;
    if (idx < D * D) {
        float w = W[idx];
        g_S[idx] = 1.0f / (1.0f + expf(-w));
    }
}

// ---------------- kernel 2: fused basis + interaction ----------------
__global__ __launch_bounds__(THREADS) void kan_kernel(const float* __restrict__ x,
                                                      float* __restrict__ out) {
    __shared__ float x_s[ROWS * XS_STRIDE];   // raw x tile, padded
    __shared__ float x2p_s[D * ROWS];         // x^2, transposed: [i][row]

    const int tid = threadIdx.x;
    const int r0 = blockIdx.x * ROWS;

    // ---- load x tile: 32 rows x 128 f32 = 1024 float4 (coalesced) ----
    const float4* xg = (const float4*)(x + (size_t)r0 * D);
#pragma unroll
    for (int k = 0; k < 4; k++) {
        int q = tid + k * 256;              // 0..1023
        int row = q >> 5;
        int c4 = q & 31;
        float4 v = xg[row * 32 + c4];
        float* dst = &x_s[row * XS_STRIDE + c4 * 4];
        dst[0] = v.x; dst[1] = v.y; dst[2] = v.z; dst[3] = v.w;
    }
    __syncthreads();

    // ---- transpose + square into x2p_s (conflict-free writes) ----
#pragma unroll
    for (int k = 0; k < 16; k++) {
        int idx = tid + k * 256;            // 0..4095
        int row = idx & 31;                 // lanes span rows -> STS conflict-free
        int i = idx >> 5;
        float v = x_s[row * XS_STRIDE + i]; // stride 129 -> LDS conflict-free
        x2p_s[i * ROWS + row] = v * v;
    }
    __syncthreads();

    // ---- phase A: B-spline basis (uniform cubic, closed form) ----
    // DENSE store mapping: each thread owns one float2 slot of the output
    // basis region, so consecutive lanes hit consecutive 8B addresses and
    // every warp STG.64 is a full 256B (2 wavefronts, zero amplification).
    // Slot q (0..12287): row = q/384, p = q%384, i = p/3, pair = p%3.
    const float s6 = 1.0f / 6.0f;
    const float xmax = 1.0f - 1e-6f;
#pragma unroll 6
    for (int k = 0; k < TOTAL_SLOTS / THREADS; k++) {   // 48 iterations
        int q = tid + k * THREADS;
        int row = q / SLOTS_PER_ROW;
        int p = q - row * SLOTS_PER_ROW;
        int i = p / 3;
        int pr = p - i * 3;                 // 0,1,2

        float xv = x_s[row * XS_STRIDE + i];
        float xc = fminf(fmaxf(xv, -1.0f), xmax);
        float pp = (xc + 1.0f) * 4.5f;      // knot spacing h = 2/9
        int j = (int)pp;
        j = max(0, min(j, 8));
        float u = pp - (float)j;
        float u2 = u * u;
        float u3 = u2 * u;
        float om = 1.0f - u;
        float N0 = om * om * om * s6;                               // idx 0
        float N1 = (3.0f * u3 - 6.0f * u2 + 4.0f) * s6;             // idx 1
        float N2 = (-3.0f * u3 + 3.0f * u2 + 3.0f * u + 1.0f) * s6; // idx 2
        float N3 = u3 * s6;                                         // idx 3

        // output floats kk0=2*pr, kk1=2*pr+1; value = N_{kk - j + 3} (else 0)
        int t0 = 2 * pr - j + 3;
        int t1 = t0 + 1;
        float v0 = 0.0f, v1 = 0.0f;
        v0 = (t0 == 0) ? N0 : v0;
        v0 = (t0 == 1) ? N1 : v0;
        v0 = (t0 == 2) ? N2 : v0;
        v0 = (t0 == 3) ? N3 : v0;
        v1 = (t1 == 0) ? N0 : v1;
        v1 = (t1 == 1) ? N1 : v1;
        v1 = (t1 == 2) ? N2 : v1;
        v1 = (t1 == 3) ? N3 : v1;

        float2* op = (float2*)(out + (size_t)(r0 + row) * OUTW) + p;
        *op = make_float2(v0, v1);
    }

    // ---- phase B: interaction GEMM  out[b, 768+c] = sum_i x2[b,i]*S[i,c] ----
    const int c = tid & 127;       // output column
    const int g = tid >> 7;        // row-half: 0 -> rows 0..15, 1 -> rows 16..31
    const int rbase = g * 16;

    unsigned long long a0 = 0ull, a1 = 0ull, a2 = 0ull, a3 = 0ull,
                       a4 = 0ull, a5 = 0ull, a6 = 0ull, a7 = 0ull;

#pragma unroll 4
    for (int i = 0; i < D; i++) {
        float s = __ldg(&g_S[i * D + c]);   // coalesced, L1-resident
        unsigned long long s2 = pack2(s, s);
        const ulonglong2* xp = (const ulonglong2*)&x2p_s[i * ROWS + rbase];
        ulonglong2 p0 = xp[0];              // rows rbase+0..3  (broadcast LDS.128)
        ulonglong2 p1 = xp[1];              // rows rbase+4..7
        ulonglong2 p2 = xp[2];              // rows rbase+8..11
        ulonglong2 p3 = xp[3];              // rows rbase+12..15
        a0 = fma2(p0.x, s2, a0);
        a1 = fma2(p0.y, s2, a1);
        a2 = fma2(p1.x, s2, a2);
        a3 = fma2(p1.y, s2, a3);
        a4 = fma2(p2.x, s2, a4);
        a5 = fma2(p2.y, s2, a5);
        a6 = fma2(p3.x, s2, a6);
        a7 = fma2(p3.y, s2, a7);
    }

    float lo, hi;
    float* ob = out + 768 + c;
    size_t rs = (size_t)(r0 + rbase) * OUTW;
    unpack2(a0, lo, hi); ob[rs] = lo;            ob[rs + OUTW] = hi;
    unpack2(a1, lo, hi); ob[rs + 2*OUTW] = lo;   ob[rs + 3*OUTW] = hi;
    unpack2(a2, lo, hi); ob[rs + 4*OUTW] = lo;   ob[rs + 5*OUTW] = hi;
    unpack2(a3, lo, hi); ob[rs + 6*OUTW] = lo;   ob[rs + 7*OUTW] = hi;
    unpack2(a4, lo, hi); ob[rs + 8*OUTW] = lo;   ob[rs + 9*OUTW] = hi;
    unpack2(a5, lo, hi); ob[rs + 10*OUTW] = lo;  ob[rs + 11*OUTW] = hi;
    unpack2(a6, lo, hi); ob[rs + 12*OUTW] = lo;  ob[rs + 13*OUTW] = hi;
    unpack2(a7, lo, hi); ob[rs + 14*OUTW] = lo;  ob[rs + 15*OUTW] = hi;
}

extern "C" void kernel_launch(void* const* d_in, const int* in_sizes, int n_in,
                              void* d_out, int out_size) {
    const float* x;
    const float* W;
    if (n_in >= 2 && in_sizes[0] == D * D && in_sizes[1] != D * D) {
        W = (const float*)d_in[0];
        x = (const float*)d_in[1];
    } else {
        x = (const float*)d_in[0];
        W = (const float*)d_in[1];
    }
    float* out = (float*)d_out;

    sigmoid_kernel<<<(D * D + 255) / 256, 256>>>(W);
    kan_kernel<<<BATCH / ROWS, THREADS>>>(x, out);
}